// round 5
// baseline (speedup 1.0000x reference)
#include <cuda_runtime.h>
#include <cstdint>

#define BATCH 16
#define NTOK  16384
#define CH    64
#define NKV   256

// scratch (allocation-free): K stored transposed [b][d][t], V natural [b][t][d]
__device__ float g_k[BATCH * CH * NKV];
__device__ float g_v[BATCH * NKV * CH];

__device__ __forceinline__ void fma1x4(float* acc, float a, float4 b) {
    acc[0] += a * b.x; acc[1] += a * b.y; acc[2] += a * b.z; acc[3] += a * b.w;
}
__device__ __forceinline__ void fma4x4(float (&acc)[4][4], float4 a, float4 b) {
    fma1x4(acc[0], a.x, b); fma1x4(acc[1], a.y, b);
    fma1x4(acc[2], a.z, b); fma1x4(acc[3], a.w, b);
}

// ============================================================================
// Kernel 1: strided conv (8x8, stride 8) + bias + LayerNorm + KV projection
// grid = 128 blocks (32 kv-tokens each), 256 threads
// ============================================================================
__global__ __launch_bounds__(256) void conv_kv_kernel(
    const float* __restrict__ x, const float* __restrict__ convw,
    const float* __restrict__ convb, const float* __restrict__ gamma,
    const float* __restrict__ beta, const float* __restrict__ Wkv,
    const float* __restrict__ bkv)
{
    __shared__ float sA[64 * 64];   // conv_w panel [ci][co]
    __shared__ float sX[64 * 32];   // patch panel, transposed [ci][tok]
    __shared__ float sC[64 * 32];   // conv out / normalized x, [co][tok]
    __shared__ float sSum[8 * 32];
    __shared__ float sSq[8 * 32];
    __shared__ float sMean[32];
    __shared__ float sRstd[32];

    const int tid = threadIdx.x;
    const int tx  = tid & 15, ty = tid >> 4;
    const int t0  = blockIdx.x * 32;     // global kv-token base (same batch for all 32)
    const int b   = t0 >> 8;

    // per-thread patch-load mapping: token tt, 8 input channels starting at ci0
    const int tt  = tid & 31;
    const int ci0 = (tid >> 5) * 8;
    const int gb  = (t0 + tt) & 255;
    const int ph  = gb >> 4, pw = gb & 15;
    const float* xb = x + (size_t)b * NTOK * CH;

    float acc[4][2];
    #pragma unroll
    for (int u = 0; u < 4; u++) { acc[u][0] = 0.f; acc[u][1] = 0.f; }

    // K = 4096 reduction, as 64 panels of 64 (one per kernel position i,j)
    for (int ij = 0; ij < 64; ij++) {
        const int i = ij >> 3, j = ij & 7;
        __syncthreads();
        {   // conv_w[(i,j)] panel: [ci][co] contiguous -> straight copy
            const float4* Ag = (const float4*)(convw + ij * 4096);
            float4* As = (float4*)sA;
            #pragma unroll
            for (int r = 0; r < 4; r++) As[tid + r * 256] = Ag[tid + r * 256];
        }
        {   // patch values x[b, ph*8+i, pw*8+j, ci] -> sX[ci][tok]
            const int row = ph * 8 + i, col = pw * 8 + j;
            const float* xr = xb + (size_t)(row * 128 + col) * CH + ci0;
            float4 v0 = *(const float4*)xr;
            float4 v1 = *(const float4*)(xr + 4);
            sX[(ci0 + 0) * 32 + tt] = v0.x; sX[(ci0 + 1) * 32 + tt] = v0.y;
            sX[(ci0 + 2) * 32 + tt] = v0.z; sX[(ci0 + 3) * 32 + tt] = v0.w;
            sX[(ci0 + 4) * 32 + tt] = v1.x; sX[(ci0 + 5) * 32 + tt] = v1.y;
            sX[(ci0 + 6) * 32 + tt] = v1.z; sX[(ci0 + 7) * 32 + tt] = v1.w;
        }
        __syncthreads();
        #pragma unroll 8
        for (int kk = 0; kk < 64; kk++) {
            float4 a = *(const float4*)&sA[kk * 64 + ty * 4];   // 4 couts
            float2 bb = *(const float2*)&sX[kk * 32 + tx * 2];  // 2 tokens
            acc[0][0] += a.x * bb.x; acc[0][1] += a.x * bb.y;
            acc[1][0] += a.y * bb.x; acc[1][1] += a.y * bb.y;
            acc[2][0] += a.z * bb.x; acc[2][1] += a.z * bb.y;
            acc[3][0] += a.w * bb.x; acc[3][1] += a.w * bb.y;
        }
    }
    __syncthreads();
    // conv bias, stage to sC[co][tok]
    #pragma unroll
    for (int u = 0; u < 4; u++) {
        const int co = ty * 4 + u;
        const float bias = convb[co];
        sC[co * 32 + tx * 2]     = acc[u][0] + bias;
        sC[co * 32 + tx * 2 + 1] = acc[u][1] + bias;
    }
    __syncthreads();
    // LayerNorm over 64 channels per token (8 threads/token partial sums)
    {
        const int tk = tid & 31, pr = tid >> 5;
        float s = 0.f, sq = 0.f;
        #pragma unroll
        for (int c = 0; c < 8; c++) {
            float v = sC[(pr * 8 + c) * 32 + tk];
            s += v; sq += v * v;
        }
        sSum[pr * 32 + tk] = s; sSq[pr * 32 + tk] = sq;
    }
    __syncthreads();
    if (tid < 32) {
        float s = 0.f, sq = 0.f;
        #pragma unroll
        for (int pr = 0; pr < 8; pr++) { s += sSum[pr * 32 + tid]; sq += sSq[pr * 32 + tid]; }
        const float mean = s * (1.f / 64.f);
        const float var  = sq * (1.f / 64.f) - mean * mean;
        sMean[tid] = mean;
        sRstd[tid] = rsqrtf(var + 1e-5f);
    }
    __syncthreads();
    {
        const int tk = tid & 31, pr = tid >> 5;
        const float mean = sMean[tk], r = sRstd[tk];
        #pragma unroll
        for (int c = 0; c < 8; c++) {
            const int cc = pr * 8 + c;
            sC[cc * 32 + tk] = (sC[cc * 32 + tk] - mean) * r * gamma[cc] + beta[cc];
        }
    }
    __syncthreads();
    // KV projection: kv[tok][o] = sum_c xn[tok][c] * Wkv[c][o], o in [0,128)
    float kv[8][2];
    #pragma unroll
    for (int u = 0; u < 8; u++) { kv[u][0] = 0.f; kv[u][1] = 0.f; }
    #pragma unroll 4
    for (int kk = 0; kk < 64; kk++) {
        float2 bb = *(const float2*)&sC[kk * 32 + tx * 2];
        const float* wr = Wkv + kk * 128 + ty * 8;
        #pragma unroll
        for (int u = 0; u < 8; u++) {
            float a = __ldg(wr + u);
            kv[u][0] += a * bb.x; kv[u][1] += a * bb.y;
        }
    }
    const int tok0 = (t0 & 255) + tx * 2;
    #pragma unroll
    for (int u = 0; u < 8; u++) {
        const int o = ty * 8 + u;
        const float bb = bkv[o];
        const float r0 = kv[u][0] + bb, r1 = kv[u][1] + bb;
        if (o < 64) {   // K, stored transposed [b][d][t]
            float* kp = g_k + ((size_t)b * 64 + o) * 256 + tok0;
            kp[0] = r0; kp[1] = r1;
        } else {        // V, natural [b][t][d]
            float* vp = g_v + ((size_t)b * 256 + tok0) * 64 + (o - 64);
            vp[0] = r0; vp[64] = r1;
        }
    }
}

// ============================================================================
// Kernel 2: per 64-query tile: Q-proj -> S=QK^T -> softmax -> O=PV -> Y=OWo+bo
// grid = (256 qtiles, 16 batches), 256 threads, 176 KB dynamic smem
// ============================================================================
__global__ __launch_bounds__(256) void attn_kernel(
    const float* __restrict__ x, const float* __restrict__ Wq,
    const float* __restrict__ bq, const float* __restrict__ Wo,
    const float* __restrict__ bo, float* __restrict__ out)
{
    extern __shared__ float sm[];
    float* sW   = sm;            // 4096: Wq, later Wo            [c][d] / [d][e]
    float* sAux = sm + 4096;     // 4096: Xt [c][tok], later softmax scratch
    float* sQt  = sm + 8192;     // 4096: Qt [d][tok], later Ot [d][tok]
    float* sKV  = sm + 12288;    // 16384: Kt [d][j], later V [j][d]
    float* sSt  = sm + 28672;    // 16384: St/Pt [j][tok]

    const int tid = threadIdx.x;
    const int tx  = tid & 15, ty = tid >> 4;
    const int b   = blockIdx.y;
    const int q0  = blockIdx.x * 64;

    // ---- stage Wq, X-tile (transposed), Kt ----
    {
        const float4* src = (const float4*)Wq;
        float4* dst = (float4*)sW;
        #pragma unroll
        for (int r = 0; r < 4; r++) dst[tid + r * 256] = src[tid + r * 256];
    }
    {
        const int tok = tid & 63, c0 = (tid >> 6) * 16;
        const float* xr = x + ((size_t)(b * NTOK + q0 + tok)) * CH + c0;
        #pragma unroll
        for (int r = 0; r < 4; r++) {
            float4 v = *(const float4*)(xr + r * 4);
            sAux[(c0 + r * 4 + 0) * 64 + tok] = v.x;
            sAux[(c0 + r * 4 + 1) * 64 + tok] = v.y;
            sAux[(c0 + r * 4 + 2) * 64 + tok] = v.z;
            sAux[(c0 + r * 4 + 3) * 64 + tok] = v.w;
        }
    }
    {
        const float4* src = (const float4*)(g_k + (size_t)b * CH * NKV);
        float4* dst = (float4*)sKV;
        #pragma unroll
        for (int r = 0; r < 16; r++) dst[tid + r * 256] = src[tid + r * 256];
    }
    __syncthreads();

    // ---- GEMM1: Qt[d][tok] = sum_c Wq[c][d] * Xt[c][tok] + bq[d] ----
    {
        float acc[4][4];
        #pragma unroll
        for (int u = 0; u < 4; u++) { acc[u][0]=acc[u][1]=acc[u][2]=acc[u][3]=0.f; }
        #pragma unroll 8
        for (int kk = 0; kk < 64; kk++) {
            float4 a  = *(const float4*)&sW  [kk * 64 + ty * 4];  // d-frag
            float4 bv = *(const float4*)&sAux[kk * 64 + tx * 4];  // tok-frag
            fma4x4(acc, a, bv);
        }
        #pragma unroll
        for (int u = 0; u < 4; u++) {
            const float bqv = __ldg(bq + ty * 4 + u);
            float4 r = make_float4(acc[u][0]+bqv, acc[u][1]+bqv, acc[u][2]+bqv, acc[u][3]+bqv);
            *(float4*)&sQt[(ty * 4 + u) * 64 + tx * 4] = r;
        }
    }
    __syncthreads();

    // ---- GEMM2: St[j][tok] = 0.125 * sum_d Kt[d][j] * Qt[d][tok] ----
    {
        float acc[16][4];
        #pragma unroll
        for (int u = 0; u < 16; u++) { acc[u][0]=acc[u][1]=acc[u][2]=acc[u][3]=0.f; }
        #pragma unroll 2
        for (int kk = 0; kk < 64; kk++) {
            float4 bv = *(const float4*)&sQt[kk * 64 + tx * 4];
            #pragma unroll
            for (int um = 0; um < 4; um++) {
                float4 a = *(const float4*)&sKV[kk * 256 + ty * 16 + um * 4];
                fma1x4(acc[um * 4 + 0], a.x, bv);
                fma1x4(acc[um * 4 + 1], a.y, bv);
                fma1x4(acc[um * 4 + 2], a.z, bv);
                fma1x4(acc[um * 4 + 3], a.w, bv);
            }
        }
        #pragma unroll
        for (int u = 0; u < 16; u++) {
            float4 r = make_float4(acc[u][0]*0.125f, acc[u][1]*0.125f,
                                   acc[u][2]*0.125f, acc[u][3]*0.125f);
            *(float4*)&sSt[(ty * 16 + u) * 64 + tx * 4] = r;
        }
    }
    __syncthreads();

    // ---- stage V and Wo (global latency overlapped with softmax) ----
    {
        const float4* src = (const float4*)(g_v + (size_t)b * NKV * CH);
        float4* dst = (float4*)sKV;
        #pragma unroll
        for (int r = 0; r < 16; r++) dst[tid + r * 256] = src[tid + r * 256];
    }
    {
        const float4* src = (const float4*)Wo;
        float4* dst = (float4*)sW;
        #pragma unroll
        for (int r = 0; r < 4; r++) dst[tid + r * 256] = src[tid + r * 256];
    }

    // ---- softmax over j per token column (4 threads/token) ----
    float* pm = sAux;         // [4][64] partial max
    float* gm = sAux + 256;   // [64] global max
    float* ps = sAux + 320;   // [4][64] partial sums
    float* gl = sAux + 576;   // [64] 1/sum
    const int tk = tid & 63, pr = tid >> 6;
    {
        float m = -1e30f;
        #pragma unroll 8
        for (int j = pr * 64; j < pr * 64 + 64; j++) m = fmaxf(m, sSt[j * 64 + tk]);
        pm[pr * 64 + tk] = m;
    }
    __syncthreads();
    if (tid < 64)
        gm[tid] = fmaxf(fmaxf(pm[tid], pm[64 + tid]), fmaxf(pm[128 + tid], pm[192 + tid]));
    __syncthreads();
    {
        const float m = gm[tk];
        float s = 0.f;
        #pragma unroll 8
        for (int j = pr * 64; j < pr * 64 + 64; j++) {
            float e = __expf(sSt[j * 64 + tk] - m);
            sSt[j * 64 + tk] = e;
            s += e;
        }
        ps[pr * 64 + tk] = s;
    }
    __syncthreads();
    if (tid < 64)
        gl[tid] = 1.f / (ps[tid] + ps[64 + tid] + ps[128 + tid] + ps[192 + tid]);
    __syncthreads();

    // ---- GEMM3: Ot[d][tok] = (sum_j V[j][d] * P[j][tok]) * (1/l[tok]) ----
    {
        float acc[4][4];
        #pragma unroll
        for (int u = 0; u < 4; u++) { acc[u][0]=acc[u][1]=acc[u][2]=acc[u][3]=0.f; }
        #pragma unroll 4
        for (int kk = 0; kk < 256; kk++) {
            float4 a  = *(const float4*)&sKV[kk * 64 + ty * 4];  // d-frag
            float4 bv = *(const float4*)&sSt[kk * 64 + tx * 4];  // tok-frag
            fma4x4(acc, a, bv);
        }
        const float l0 = gl[tx * 4 + 0], l1 = gl[tx * 4 + 1];
        const float l2 = gl[tx * 4 + 2], l3 = gl[tx * 4 + 3];
        #pragma unroll
        for (int u = 0; u < 4; u++) {
            float4 r = make_float4(acc[u][0]*l0, acc[u][1]*l1, acc[u][2]*l2, acc[u][3]*l3);
            *(float4*)&sQt[(ty * 4 + u) * 64 + tx * 4] = r;   // Ot reuses Qt region
        }
    }
    __syncthreads();

    // ---- GEMM4: Y[tok][e] = sum_d Ot[d][tok] * Wo[d][e] + bo[e] ----
    {
        float acc[4][4];
        #pragma unroll
        for (int u = 0; u < 4; u++) { acc[u][0]=acc[u][1]=acc[u][2]=acc[u][3]=0.f; }
        #pragma unroll 8
        for (int kk = 0; kk < 64; kk++) {
            float4 a  = *(const float4*)&sQt[kk * 64 + ty * 4];  // tok-frag
            float4 bv = *(const float4*)&sW [kk * 64 + tx * 4];  // e-frag
            fma4x4(acc, a, bv);
        }
        const float4 bo4 = *(const float4*)(bo + tx * 4);
        #pragma unroll
        for (int u = 0; u < 4; u++) {
            float4 r = make_float4(acc[u][0]+bo4.x, acc[u][1]+bo4.y,
                                   acc[u][2]+bo4.z, acc[u][3]+bo4.w);
            *(float4*)&out[((size_t)(b * NTOK + q0 + ty * 4 + u)) * CH + tx * 4] = r;
        }
    }
}

extern "C" void kernel_launch(void* const* d_in, const int* in_sizes, int n_in,
                              void* d_out, int out_size)
{
    const float* inputs = (const float*)d_in[0];
    const float* Wq     = (const float*)d_in[1];
    const float* bq     = (const float*)d_in[2];
    const float* Wkv    = (const float*)d_in[3];
    const float* bkv    = (const float*)d_in[4];
    const float* Wo     = (const float*)d_in[5];
    const float* bo     = (const float*)d_in[6];
    const float* convw  = (const float*)d_in[7];
    const float* convb  = (const float*)d_in[8];
    const float* gamma  = (const float*)d_in[9];
    const float* beta   = (const float*)d_in[10];
    float* out = (float*)d_out;

    const int smem_bytes = 45056 * 4;  // 176 KB
    cudaFuncSetAttribute(attn_kernel, cudaFuncAttributeMaxDynamicSharedMemorySize, smem_bytes);

    conv_kv_kernel<<<128, 256>>>(inputs, convw, convb, gamma, beta, Wkv, bkv);
    attn_kernel<<<dim3(256, 16), 256, smem_bytes>>>(inputs, Wq, bq, Wo, bo, out);
}

// round 6
// speedup vs baseline: 2.2095x; 2.2095x over previous
#include <cuda_runtime.h>
#include <cstdint>

#define BATCH 16
#define NTOK  16384
#define CH    64
#define NKV   256

// scratch (allocation-free)
__device__ float g_k[BATCH * NKV * CH];     // K natural [b][t][d] (tf32-rounded)
__device__ float g_v[BATCH * CH * NKV];     // V transposed [b][d][t] (tf32-rounded)
__device__ float g_wqT[64 * 64];            // Wq^T [d][c] (tf32)
__device__ float g_woT[64 * 64];            // Wo^T [e][d] (tf32)
__device__ float g_wkvT[128 * 64];          // Wkv^T [o][c] (tf32)
__device__ float g_cwT[64 * 4096];          // conv_w^T [co][ij*64+ci] (tf32)

__device__ __forceinline__ uint32_t f2t(float x) {
    uint32_t u; asm("cvt.rna.tf32.f32 %0, %1;" : "=r"(u) : "f"(x)); return u;
}
__device__ __forceinline__ float f2tf(float x) { return __uint_as_float(f2t(x)); }

__device__ __forceinline__ void mma8(float* d, const uint32_t* a, const uint32_t* b) {
    asm volatile(
        "mma.sync.aligned.m16n8k8.row.col.f32.tf32.tf32.f32 "
        "{%0,%1,%2,%3},{%4,%5,%6,%7},{%8,%9},{%0,%1,%2,%3};"
        : "+f"(d[0]), "+f"(d[1]), "+f"(d[2]), "+f"(d[3])
        : "r"(a[0]), "r"(a[1]), "r"(a[2]), "r"(a[3]), "r"(b[0]), "r"(b[1]));
}
// A row-major [m][k]; pa = &A[(m0+g)*s + k0 + t4]; s8 = 8*stride
__device__ __forceinline__ void ldA(uint32_t* a, const float* pa, int s8) {
    a[0] = __float_as_uint(pa[0]);  a[1] = __float_as_uint(pa[s8]);
    a[2] = __float_as_uint(pa[4]);  a[3] = __float_as_uint(pa[s8 + 4]);
}
// B col-major [n][k]; pb = &B[(n0+g)*s + k0 + t4]
__device__ __forceinline__ void ldB(uint32_t* b, const float* pb) {
    b[0] = __float_as_uint(pb[0]);  b[1] = __float_as_uint(pb[4]);
}

// ============================================================================
// prep: transpose + tf32-round all weight matrices (runs once per launch)
// ============================================================================
__global__ __launch_bounds__(256) void prep_kernel(
    const float* __restrict__ Wq, const float* __restrict__ Wo,
    const float* __restrict__ Wkv, const float* __restrict__ cw)
{
    int i = blockIdx.x * 256 + threadIdx.x;
    if (i < 4096) {
        int d = i >> 6, c = i & 63;
        g_wqT[i] = f2tf(Wq[c * 64 + d]);
    } else if (i < 8192) {
        int j = i - 4096, e = j >> 6, d = j & 63;
        g_woT[j] = f2tf(Wo[d * 64 + e]);
    } else if (i < 16384) {
        int j = i - 8192, o = j >> 6, c = j & 63;
        g_wkvT[j] = f2tf(Wkv[c * 128 + o]);
    } else if (i < 278528) {
        int j = i - 16384, co = j >> 12, k = j & 4095;
        g_cwT[j] = f2tf(cw[k * 64 + co]);
    }
}

// ============================================================================
// Kernel 1: strided conv (8x8, s8) + bias + LN + KV proj, all on tensor mma
// grid = 128 blocks (32 kv-tokens), 256 threads, static smem ~45 KB
// ============================================================================
__global__ __launch_bounds__(256) void conv_kv_kernel(
    const float* __restrict__ x, const float* __restrict__ convb,
    const float* __restrict__ gamma, const float* __restrict__ beta,
    const float* __restrict__ bkv)
{
    __shared__ float sC[32 * 68];    // A: patches [tok][ci]; later conv-out / xn
    __shared__ float sB[128 * 68];   // B: weight panel [co][ci]; later WkvT [o][c]
    __shared__ float aux[576];       // 256 sum + 256 sq + 32 mean + 32 rstd

    const int tid = threadIdx.x;
    const int w = tid >> 5, lane = tid & 31, g = lane >> 2, t4 = lane & 3;
    const int t0 = blockIdx.x * 32, b = t0 >> 8;
    const int mi = w & 1, m0 = mi * 16;

    // patch staging mapping
    const int tt = tid & 31, ci0 = (tid >> 5) * 8;
    const int gb = (t0 + tt) & 255, ph = gb >> 4, pw = gb & 15;
    const float* xb = x + (size_t)b * NTOK * CH;

    float acc1[2][4];
    #pragma unroll
    for (int n = 0; n < 2; n++) { acc1[n][0]=acc1[n][1]=acc1[n][2]=acc1[n][3]=0.f; }

    for (int ij = 0; ij < 64; ij++) {
        __syncthreads();
        {   // stage A: patches [tok][ci] (tf32-rounded)
            const int row = ph * 8 + (ij >> 3), col = pw * 8 + (ij & 7);
            const float* xr = xb + (size_t)(row * 128 + col) * CH + ci0;
            float4 v0 = *(const float4*)xr, v1 = *(const float4*)(xr + 4);
            *(float4*)&sC[tt * 68 + ci0]     = make_float4(f2tf(v0.x), f2tf(v0.y), f2tf(v0.z), f2tf(v0.w));
            *(float4*)&sC[tt * 68 + ci0 + 4] = make_float4(f2tf(v1.x), f2tf(v1.y), f2tf(v1.z), f2tf(v1.w));
        }
        #pragma unroll
        for (int r = 0; r < 4; r++) {   // stage B panel [co][ci] from g_cwT
            int pos = tid + r * 256, co = pos >> 4, c4 = pos & 15;
            *(float4*)&sB[co * 68 + c4 * 4] =
                *(const float4*)&g_cwT[co * 4096 + ij * 64 + c4 * 4];
        }
        __syncthreads();
        #pragma unroll
        for (int k0 = 0; k0 < 64; k0 += 8) {
            uint32_t a[4]; ldA(a, &sC[(m0 + g) * 68 + k0 + t4], 544);
            #pragma unroll
            for (int n = 0; n < 2; n++) {
                uint32_t bb[2]; ldB(bb, &sB[(((w >> 1) * 2 + n) * 8 + g) * 68 + k0 + t4]);
                mma8(acc1[n], a, bb);
            }
        }
    }
    __syncthreads();
    // conv-out + bias -> sC[tok][co] (fp32, for LN)
    #pragma unroll
    for (int n = 0; n < 2; n++) {
        int c0 = ((w >> 1) * 2 + n) * 8 + 2 * t4;
        float2 bc = *(const float2*)&convb[c0];
        *(float2*)&sC[(m0 + g) * 68 + c0]     = make_float2(acc1[n][0] + bc.x, acc1[n][1] + bc.y);
        *(float2*)&sC[(m0 + g + 8) * 68 + c0] = make_float2(acc1[n][2] + bc.x, acc1[n][3] + bc.y);
    }
    __syncthreads();
    // stage WkvT (overlaps with LN math)
    #pragma unroll
    for (int r = 0; r < 8; r++) {
        int pos = tid + r * 256, o = pos >> 4, c4 = pos & 15;
        *(float4*)&sB[o * 68 + c4 * 4] = *(const float4*)&g_wkvT[o * 64 + c4 * 4];
    }
    // LayerNorm
    {
        int tok = tid & 31, pr = tid >> 5;
        float4 u0 = *(float4*)&sC[tok * 68 + pr * 8];
        float4 u1 = *(float4*)&sC[tok * 68 + pr * 8 + 4];
        float s  = u0.x + u0.y + u0.z + u0.w + u1.x + u1.y + u1.z + u1.w;
        float sq = u0.x*u0.x + u0.y*u0.y + u0.z*u0.z + u0.w*u0.w
                 + u1.x*u1.x + u1.y*u1.y + u1.z*u1.z + u1.w*u1.w;
        aux[pr * 32 + tok] = s; aux[256 + pr * 32 + tok] = sq;
    }
    __syncthreads();
    if (tid < 32) {
        float s = 0.f, sq = 0.f;
        #pragma unroll
        for (int p = 0; p < 8; p++) { s += aux[p * 32 + tid]; sq += aux[256 + p * 32 + tid]; }
        float mean = s * (1.f / 64.f);
        float var  = sq * (1.f / 64.f) - mean * mean;
        aux[512 + tid] = mean; aux[544 + tid] = rsqrtf(var + 1e-5f);
    }
    __syncthreads();
    {
        int tok = tid & 31, pr = tid >> 5;
        float mean = aux[512 + tok], r = aux[544 + tok];
        #pragma unroll
        for (int u = 0; u < 8; u++) {
            int c = pr * 8 + u;
            float v = sC[tok * 68 + c];
            sC[tok * 68 + c] = f2tf((v - mean) * r * __ldg(gamma + c) + __ldg(beta + c));
        }
    }
    __syncthreads();
    // KV GEMM: [32 tok] x [128 o], k=64
    float acc2[4][4];
    #pragma unroll
    for (int n = 0; n < 4; n++) { acc2[n][0]=acc2[n][1]=acc2[n][2]=acc2[n][3]=0.f; }
    #pragma unroll
    for (int k0 = 0; k0 < 64; k0 += 8) {
        uint32_t a[4]; ldA(a, &sC[(m0 + g) * 68 + k0 + t4], 544);
        #pragma unroll
        for (int n = 0; n < 4; n++) {
            uint32_t bb[2]; ldB(bb, &sB[(((w >> 1) * 4 + n) * 8 + g) * 68 + k0 + t4]);
            mma8(acc2[n], a, bb);
        }
    }
    const int tloc = t0 & 255;
    #pragma unroll
    for (int n = 0; n < 4; n++) {
        int c0 = ((w >> 1) * 4 + n) * 8 + 2 * t4;
        float bk0 = __ldg(bkv + c0), bk1 = __ldg(bkv + c0 + 1);
        #pragma unroll
        for (int h = 0; h < 2; h++) {
            int row = m0 + g + h * 8;
            float r0 = f2tf(acc2[n][2 * h + 0] + bk0);
            float r1 = f2tf(acc2[n][2 * h + 1] + bk1);
            if (c0 < 64) {   // K natural [b][t][d]
                g_k[(size_t)(t0 + row) * 64 + c0]     = r0;
                g_k[(size_t)(t0 + row) * 64 + c0 + 1] = r1;
            } else {         // V transposed [b][d][t]
                g_v[(size_t)(b * 64 + c0 - 64) * 256 + tloc + row] = r0;
                g_v[(size_t)(b * 64 + c0 - 63) * 256 + tloc + row] = r1;
            }
        }
    }
}

// ============================================================================
// Kernel 2: 64-query tile: Q-proj -> S=QK^T -> softmax -> O=PV -> Y=OWo+bo
// grid = (256, 16), 256 threads, ~186 KB dynamic smem, all GEMMs on mma.tf32
// ============================================================================
__global__ __launch_bounds__(256) void attn_kernel(
    const float* __restrict__ x, const float* __restrict__ bq,
    const float* __restrict__ bo, float* __restrict__ out)
{
    extern __shared__ float sm[];
    float* sX  = sm;             // 64x68 : X [tok][c] (tf32)
    float* sWt = sm + 4352;      // 64x68 : WqT [d][c], later WoT [e][d]
    float* sQ  = sm + 8704;      // 64x68 : Q [tok][d] (tf32, pre-scaled), later O
    float* sK  = sm + 13056;     // 256x68: K [j][d]; later Vt [d][j] (64x260)
    float* sS  = sm + 30464;     // 64x260: S/P [tok][j]
    float* aux = sm + 47104;     // 256 pmax + 256 psum + 64 invl

    const int tid = threadIdx.x;
    const int w = tid >> 5, lane = tid & 31, g = lane >> 2, t4 = lane & 3;
    const int b = blockIdx.y, q0 = blockIdx.x * 64;
    const int mi = w & 3, nh = w >> 2;           // m-tile, n-half
    const int m0 = mi * 16;

    // ---- stage X (round), WqT, K ----
    #pragma unroll
    for (int r = 0; r < 4; r++) {
        int pos = tid + r * 256, tok = pos >> 4, c4 = pos & 15;
        float4 v = *(const float4*)&x[((size_t)(b * NTOK + q0 + tok)) * 64 + c4 * 4];
        *(float4*)&sX[tok * 68 + c4 * 4] = make_float4(f2tf(v.x), f2tf(v.y), f2tf(v.z), f2tf(v.w));
    }
    #pragma unroll
    for (int r = 0; r < 4; r++) {
        int pos = tid + r * 256, d = pos >> 4, c4 = pos & 15;
        *(float4*)&sWt[d * 68 + c4 * 4] = *(const float4*)&g_wqT[d * 64 + c4 * 4];
    }
    #pragma unroll
    for (int r = 0; r < 16; r++) {
        int pos = tid + r * 256, j = pos >> 4, c4 = pos & 15;
        *(float4*)&sK[j * 68 + c4 * 4] = *(const float4*)&g_k[(size_t)b * 16384 + j * 64 + c4 * 4];
    }
    __syncthreads();

    // ---- GEMM1: Q[tok][d] = (X WqT^T + bq) * 0.125, rounded ----
    {
        float acc[4][4];
        #pragma unroll
        for (int n = 0; n < 4; n++) { acc[n][0]=acc[n][1]=acc[n][2]=acc[n][3]=0.f; }
        #pragma unroll
        for (int k0 = 0; k0 < 64; k0 += 8) {
            uint32_t a[4]; ldA(a, &sX[(m0 + g) * 68 + k0 + t4], 544);
            #pragma unroll
            for (int n = 0; n < 4; n++) {
                uint32_t bb[2]; ldB(bb, &sWt[((nh * 4 + n) * 8 + g) * 68 + k0 + t4]);
                mma8(acc[n], a, bb);
            }
        }
        #pragma unroll
        for (int n = 0; n < 4; n++) {
            int c0 = (nh * 4 + n) * 8 + 2 * t4;
            float2 bb = *(const float2*)&bq[c0];
            *(float2*)&sQ[(m0 + g) * 68 + c0] =
                make_float2(f2tf((acc[n][0] + bb.x) * 0.125f), f2tf((acc[n][1] + bb.y) * 0.125f));
            *(float2*)&sQ[(m0 + g + 8) * 68 + c0] =
                make_float2(f2tf((acc[n][2] + bb.x) * 0.125f), f2tf((acc[n][3] + bb.y) * 0.125f));
        }
    }
    __syncthreads();

    // ---- GEMM2: S[tok][j] = Q K^T  (m=64, n=256, k=64) ----
    {
        float acc[16][4];
        #pragma unroll
        for (int n = 0; n < 16; n++) { acc[n][0]=acc[n][1]=acc[n][2]=acc[n][3]=0.f; }
        #pragma unroll
        for (int k0 = 0; k0 < 64; k0 += 8) {
            uint32_t a[4]; ldA(a, &sQ[(m0 + g) * 68 + k0 + t4], 544);
            #pragma unroll
            for (int n = 0; n < 16; n++) {
                uint32_t bb[2]; ldB(bb, &sK[((nh * 16 + n) * 8 + g) * 68 + k0 + t4]);
                mma8(acc[n], a, bb);
            }
        }
        #pragma unroll
        for (int n = 0; n < 16; n++) {
            int c0 = (nh * 16 + n) * 8 + 2 * t4;
            *(float2*)&sS[(m0 + g) * 260 + c0]     = make_float2(acc[n][0], acc[n][1]);
            *(float2*)&sS[(m0 + g + 8) * 260 + c0] = make_float2(acc[n][2], acc[n][3]);
        }
    }
    __syncthreads();

    // ---- stage Vt (over sK) + WoT (over sWt), overlapped with softmax ----
    #pragma unroll
    for (int r = 0; r < 16; r++) {
        int pos = tid + r * 256, d = pos >> 6, j4 = pos & 63;
        *(float4*)&sK[d * 260 + j4 * 4] = *(const float4*)&g_v[(size_t)b * 16384 + d * 256 + j4 * 4];
    }
    #pragma unroll
    for (int r = 0; r < 4; r++) {
        int pos = tid + r * 256, e = pos >> 4, c4 = pos & 15;
        *(float4*)&sWt[e * 68 + c4 * 4] = *(const float4*)&g_woT[e * 64 + c4 * 4];
    }

    // ---- softmax over j per row (4 threads/token, contiguous 64-j chunks) ----
    const int tok = tid & 63, pr = tid >> 6;
    {
        const float* sr = &sS[tok * 260 + pr * 64];
        float m = -1e30f;
        #pragma unroll
        for (int i = 0; i < 16; i++) {
            float4 v = *(const float4*)&sr[i * 4];
            m = fmaxf(m, fmaxf(fmaxf(v.x, v.y), fmaxf(v.z, v.w)));
        }
        aux[pr * 64 + tok] = m;
    }
    __syncthreads();
    {
        float m = fmaxf(fmaxf(aux[tok], aux[64 + tok]), fmaxf(aux[128 + tok], aux[192 + tok]));
        float* sr = &sS[tok * 260 + pr * 64];
        float s = 0.f;
        #pragma unroll
        for (int i = 0; i < 16; i++) {
            float4 v = *(float4*)&sr[i * 4];
            v.x = __expf(v.x - m); v.y = __expf(v.y - m);
            v.z = __expf(v.z - m); v.w = __expf(v.w - m);
            s += v.x + v.y + v.z + v.w;
            *(float4*)&sr[i * 4] = make_float4(f2tf(v.x), f2tf(v.y), f2tf(v.z), f2tf(v.w));
        }
        aux[256 + pr * 64 + tok] = s;
    }
    __syncthreads();
    if (pr == 0)
        aux[512 + tok] = 1.f / (aux[256 + tok] + aux[320 + tok] + aux[384 + tok] + aux[448 + tok]);
    __syncthreads();

    // ---- GEMM3: O[tok][d] = (P Vt^T) * invl[tok]  (m=64, n=64, k=256) ----
    {
        float acc[4][4];
        #pragma unroll
        for (int n = 0; n < 4; n++) { acc[n][0]=acc[n][1]=acc[n][2]=acc[n][3]=0.f; }
        #pragma unroll
        for (int k0 = 0; k0 < 256; k0 += 8) {
            uint32_t a[4]; ldA(a, &sS[(m0 + g) * 260 + k0 + t4], 2080);
            #pragma unroll
            for (int n = 0; n < 4; n++) {
                uint32_t bb[2]; ldB(bb, &sK[((nh * 4 + n) * 8 + g) * 260 + k0 + t4]);
                mma8(acc[n], a, bb);
            }
        }
        float li0 = aux[512 + m0 + g], li1 = aux[512 + m0 + g + 8];
        #pragma unroll
        for (int n = 0; n < 4; n++) {
            int c0 = (nh * 4 + n) * 8 + 2 * t4;
            *(float2*)&sQ[(m0 + g) * 68 + c0] =
                make_float2(f2tf(acc[n][0] * li0), f2tf(acc[n][1] * li0));
            *(float2*)&sQ[(m0 + g + 8) * 68 + c0] =
                make_float2(f2tf(acc[n][2] * li1), f2tf(acc[n][3] * li1));
        }
    }
    __syncthreads();

    // ---- GEMM4: Y[tok][e] = O WoT^T + bo -> gmem ----
    {
        float acc[4][4];
        #pragma unroll
        for (int n = 0; n < 4; n++) { acc[n][0]=acc[n][1]=acc[n][2]=acc[n][3]=0.f; }
        #pragma unroll
        for (int k0 = 0; k0 < 64; k0 += 8) {
            uint32_t a[4]; ldA(a, &sQ[(m0 + g) * 68 + k0 + t4], 544);
            #pragma unroll
            for (int n = 0; n < 4; n++) {
                uint32_t bb[2]; ldB(bb, &sWt[((nh * 4 + n) * 8 + g) * 68 + k0 + t4]);
                mma8(acc[n], a, bb);
            }
        }
        #pragma unroll
        for (int n = 0; n < 4; n++) {
            int c0 = (nh * 4 + n) * 8 + 2 * t4;
            float2 bb = *(const float2*)&bo[c0];
            size_t rb = ((size_t)(b * NTOK + q0 + m0 + g)) * 64;
            *(float2*)&out[rb + c0]          = make_float2(acc[n][0] + bb.x, acc[n][1] + bb.y);
            *(float2*)&out[rb + 8 * 64 + c0] = make_float2(acc[n][2] + bb.x, acc[n][3] + bb.y);
        }
    }
}

extern "C" void kernel_launch(void* const* d_in, const int* in_sizes, int n_in,
                              void* d_out, int out_size)
{
    const float* inputs = (const float*)d_in[0];
    const float* Wq     = (const float*)d_in[1];
    const float* bq     = (const float*)d_in[2];
    const float* Wkv    = (const float*)d_in[3];
    const float* bkv    = (const float*)d_in[4];
    const float* Wo     = (const float*)d_in[5];
    const float* bo     = (const float*)d_in[6];
    const float* convw  = (const float*)d_in[7];
    const float* convb  = (const float*)d_in[8];
    const float* gamma  = (const float*)d_in[9];
    const float* beta   = (const float*)d_in[10];
    float* out = (float*)d_out;

    const int smem_bytes = 47680 * 4;   // ~186 KB
    cudaFuncSetAttribute(attn_kernel, cudaFuncAttributeMaxDynamicSharedMemorySize, smem_bytes);

    prep_kernel<<<1088, 256>>>(Wq, Wo, Wkv, convw);
    conv_kv_kernel<<<128, 256>>>(inputs, convb, gamma, beta, bkv);
    attn_kernel<<<dim3(256, 16), 256, smem_bytes>>>(inputs, bq, bo, out);
}